// round 1
// baseline (speedup 1.0000x reference)
#include <cuda_runtime.h>
#include <cuda_bf16.h>

// Fused scaled-dot-product attention with pre-softmax score output.
// q:(B,H,S,64) k:(B,H,64,S) v:(B,H,S,64) prev:(B,H,S,S)
// d_out = [ out (B,H,S,64) | attn_scores (B,H,S,S) ]
#define S_LEN 2048
#define DH    64
#define BHN   32          // B*H
#define BM    64          // rows per CTA tile
#define BN    64          // column tile width
#define QK_SCALE 0.125f

__global__ __launch_bounds__(256, 2)
void attn_fused_kernel(const float* __restrict__ q,
                       const float* __restrict__ k,
                       const float* __restrict__ v,
                       const float* __restrict__ prev,
                       float* __restrict__ out_o,
                       float* __restrict__ out_s)
{
    __shared__ float Qs[BM][DH];     // 16KB, loaded once
    __shared__ float KPs[DH][BN];    // 16KB, K-tile then reused as P-tile
    __shared__ float Vs[BN][DH];     // 16KB

    const int bh   = blockIdx.y;
    const int row0 = blockIdx.x * BM;
    const int tid  = threadIdx.x;
    const int tx   = tid & 15;       // 16 col-groups of 4
    const int ty   = tid >> 4;       // 16 row-groups of 4

    const float* qb = q    + ((size_t)bh * S_LEN + row0) * DH;
    const float* kb = k    + (size_t)bh * DH * S_LEN;
    const float* vb = v    + (size_t)bh * S_LEN * DH;
    const float* pb = prev + ((size_t)bh * S_LEN + row0) * S_LEN;
    float*       sb = out_s + ((size_t)bh * S_LEN + row0) * S_LEN;
    float*       ob = out_o + ((size_t)bh * S_LEN + row0) * DH;

    // Load Q tile (64x64 floats = 1024 float4, 4 per thread)
    #pragma unroll
    for (int p = 0; p < 4; p++) {
        int idx = tid + p * 256;
        int r = idx >> 4, c4 = (idx & 15) << 2;
        *(float4*)&Qs[r][c4] = *(const float4*)&qb[(size_t)r * DH + c4];
    }

    float m[4], l[4], acc[4][4];
    #pragma unroll
    for (int i = 0; i < 4; i++) {
        m[i] = -1e30f; l[i] = 0.f;
        #pragma unroll
        for (int j = 0; j < 4; j++) acc[i][j] = 0.f;
    }

    for (int n0 = 0; n0 < S_LEN; n0 += BN) {
        __syncthreads();   // previous iteration done with KPs / Vs
        // Load K tile (K[d][n0+c]) and V tile (V[n0+t][d])
        #pragma unroll
        for (int p = 0; p < 4; p++) {
            int idx = tid + p * 256;
            int r = idx >> 4, c4 = (idx & 15) << 2;
            *(float4*)&KPs[r][c4] = *(const float4*)&kb[(size_t)r * S_LEN + n0 + c4];
            *(float4*)&Vs[r][c4]  = *(const float4*)&vb[(size_t)(n0 + r) * DH + c4];
        }
        __syncthreads();

        // --- QK^T microtile: s[4][4] ---
        float s[4][4];
        #pragma unroll
        for (int i = 0; i < 4; i++)
            #pragma unroll
            for (int j = 0; j < 4; j++) s[i][j] = 0.f;

        #pragma unroll 8
        for (int kk = 0; kk < DH; kk++) {
            float4 b = *(float4*)&KPs[kk][tx << 2];
            float a0 = Qs[(ty << 2) + 0][kk];
            float a1 = Qs[(ty << 2) + 1][kk];
            float a2 = Qs[(ty << 2) + 2][kk];
            float a3 = Qs[(ty << 2) + 3][kk];
            s[0][0] += a0 * b.x; s[0][1] += a0 * b.y; s[0][2] += a0 * b.z; s[0][3] += a0 * b.w;
            s[1][0] += a1 * b.x; s[1][1] += a1 * b.y; s[1][2] += a1 * b.z; s[1][3] += a1 * b.w;
            s[2][0] += a2 * b.x; s[2][1] += a2 * b.y; s[2][2] += a2 * b.z; s[2][3] += a2 * b.w;
            s[3][0] += a3 * b.x; s[3][1] += a3 * b.y; s[3][2] += a3 * b.z; s[3][3] += a3 * b.w;
        }

        // --- scale + prev, write scores ---
        #pragma unroll
        for (int i = 0; i < 4; i++) {
            int gr = (ty << 2) + i;
            const float4 pv = *(const float4*)&pb[(size_t)gr * S_LEN + n0 + (tx << 2)];
            s[i][0] = fmaf(s[i][0], QK_SCALE, pv.x);
            s[i][1] = fmaf(s[i][1], QK_SCALE, pv.y);
            s[i][2] = fmaf(s[i][2], QK_SCALE, pv.z);
            s[i][3] = fmaf(s[i][3], QK_SCALE, pv.w);
            float4 st = make_float4(s[i][0], s[i][1], s[i][2], s[i][3]);
            *(float4*)&sb[(size_t)gr * S_LEN + n0 + (tx << 2)] = st;
        }

        // --- online softmax update (row groups are 16 consecutive lanes) ---
        #pragma unroll
        for (int i = 0; i < 4; i++) {
            float rmax = fmaxf(fmaxf(s[i][0], s[i][1]), fmaxf(s[i][2], s[i][3]));
            #pragma unroll
            for (int sh = 8; sh >= 1; sh >>= 1)
                rmax = fmaxf(rmax, __shfl_xor_sync(0xffffffffu, rmax, sh));
            float mn = fmaxf(m[i], rmax);
            float alpha = __expf(m[i] - mn);
            m[i] = mn;
            float rsum = 0.f;
            #pragma unroll
            for (int j = 0; j < 4; j++) {
                s[i][j] = __expf(s[i][j] - mn);
                rsum += s[i][j];
            }
            #pragma unroll
            for (int sh = 8; sh >= 1; sh >>= 1)
                rsum += __shfl_xor_sync(0xffffffffu, rsum, sh);
            l[i] = l[i] * alpha + rsum;
            #pragma unroll
            for (int j = 0; j < 4; j++) acc[i][j] *= alpha;
        }

        __syncthreads();   // all done reading K tile -> overwrite with P
        #pragma unroll
        for (int i = 0; i < 4; i++) {
            float4 st = make_float4(s[i][0], s[i][1], s[i][2], s[i][3]);
            *(float4*)&KPs[(ty << 2) + i][tx << 2] = st;
        }
        __syncthreads();

        // --- P @ V microtile ---
        #pragma unroll 8
        for (int t = 0; t < BN; t++) {
            float4 vv = *(float4*)&Vs[t][tx << 2];
            float p0 = KPs[(ty << 2) + 0][t];
            float p1 = KPs[(ty << 2) + 1][t];
            float p2 = KPs[(ty << 2) + 2][t];
            float p3 = KPs[(ty << 2) + 3][t];
            acc[0][0] += p0 * vv.x; acc[0][1] += p0 * vv.y; acc[0][2] += p0 * vv.z; acc[0][3] += p0 * vv.w;
            acc[1][0] += p1 * vv.x; acc[1][1] += p1 * vv.y; acc[1][2] += p1 * vv.z; acc[1][3] += p1 * vv.w;
            acc[2][0] += p2 * vv.x; acc[2][1] += p2 * vv.y; acc[2][2] += p2 * vv.z; acc[2][3] += p2 * vv.w;
            acc[3][0] += p3 * vv.x; acc[3][1] += p3 * vv.y; acc[3][2] += p3 * vv.z; acc[3][3] += p3 * vv.w;
        }
    }

    // --- epilogue: out = acc / l ---
    #pragma unroll
    for (int i = 0; i < 4; i++) {
        float inv = 1.0f / l[i];
        float4 o = make_float4(acc[i][0] * inv, acc[i][1] * inv,
                               acc[i][2] * inv, acc[i][3] * inv);
        *(float4*)&ob[(size_t)((ty << 2) + i) * DH + (tx << 2)] = o;
    }
}

extern "C" void kernel_launch(void* const* d_in, const int* in_sizes, int n_in,
                              void* d_out, int out_size) {
    const float* q    = (const float*)d_in[0];
    const float* k    = (const float*)d_in[1];
    const float* v    = (const float*)d_in[2];
    const float* prev = (const float*)d_in[3];
    float* out_o = (float*)d_out;
    float* out_s = (float*)d_out + (size_t)BHN * S_LEN * DH;  // scores after out

    dim3 grid(S_LEN / BM, BHN);
    attn_fused_kernel<<<grid, 256>>>(q, k, v, prev, out_o, out_s);
}

// round 15
// speedup vs baseline: 1.6952x; 1.6952x over previous
#include <cuda_runtime.h>
#include <cstdint>

// Fused SDPA using warp-level mma.sync (tf32) — works on generic sm_103 target.
// q:(32,2048,64) k:(32,64,2048) v:(32,2048,64) prev:(32,2048,2048)
// d_out = [ out (32,2048,64) | attn_scores (32,2048,2048) ]
#define S_LEN 2048
#define DH    64
#define BM    128
#define BN    64
#define N_TILES (S_LEN / BN)
#define QK_SCALE 0.125f
#define STRIDE 72              // smem row stride in floats (pad 8 -> conflict-free B frags)

// smem layout (float offsets)
#define QS 0
#define KS (128 * STRIDE)
#define VS (KS + 64 * STRIDE)
#define PS (VS + 64 * STRIDE)
#define SMEM_FLOATS (PS + 128 * STRIDE)
#define SMEM_BYTES (SMEM_FLOATS * 4)

static __device__ __forceinline__ float f2tf32(float x) {
    float y; asm("cvt.rna.tf32.f32 %0, %1;" : "=f"(y) : "f"(x)); return y;
}

// exp on the FMA pipe: x -> 2^(x*log2e) via magic-number rint + deg-5 poly + bit splice.
static __device__ __forceinline__ float fexp(float x) {
    x = fmaxf(x, -87.0f);
    const float L2E = 1.44269504088896f;
    float y = fmaf(x, L2E, 12582912.0f);      // 1.5*2^23 magic: rounds to nearest int
    float r = y - 12582912.0f;                // integer part
    float f = fmaf(x, L2E, -r);               // fractional part in [-0.5, 0.5]
    float p = 1.3333558e-3f;
    p = fmaf(p, f, 9.6181291e-3f);
    p = fmaf(p, f, 5.5504109e-2f);
    p = fmaf(p, f, 2.4022651e-1f);
    p = fmaf(p, f, 6.9314718e-1f);
    p = fmaf(p, f, 1.0f);
    return __int_as_float(__float_as_int(p) + (((int)r) << 23));
}

static __device__ __forceinline__ void mma_tf32(float* d, const uint32_t* a, const uint32_t* b) {
    asm volatile(
        "mma.sync.aligned.m16n8k8.row.col.f32.tf32.tf32.f32 "
        "{%0,%1,%2,%3},{%4,%5,%6,%7},{%8,%9},{%0,%1,%2,%3};"
        : "+f"(d[0]), "+f"(d[1]), "+f"(d[2]), "+f"(d[3])
        : "r"(a[0]), "r"(a[1]), "r"(a[2]), "r"(a[3]), "r"(b[0]), "r"(b[1]));
}

__global__ void __launch_bounds__(256, 2)
attn_mma_kernel(const float* __restrict__ q,
                const float* __restrict__ k,
                const float* __restrict__ v,
                const float* __restrict__ prev,
                float* __restrict__ out_o,
                float* __restrict__ out_s)
{
    extern __shared__ float sm[];
    const int tid  = threadIdx.x;
    const int w    = tid >> 5;
    const int lane = tid & 31;
    const int g    = lane >> 2;   // group: row within mma tile
    const int tg   = lane & 3;    // thread-in-group: col selector
    const int wrow = w * 16;      // warp's first row in CTA tile

    const int bh   = blockIdx.y;
    const int row0 = blockIdx.x * BM;

    const float* qb = q    + ((size_t)bh * S_LEN + row0) * DH;
    const float* kb = k    + (size_t)bh * DH * S_LEN;
    const float* vb = v    + (size_t)bh * S_LEN * DH;
    const float* pb = prev + ((size_t)bh * S_LEN + row0) * S_LEN;
    float*       sb = out_s + ((size_t)bh * S_LEN + row0) * S_LEN;
    float*       ob = out_o + ((size_t)bh * S_LEN + row0) * DH;

    // ---- Q tile -> smem (tf32), resident all kernel ----
    for (int idx = tid; idx < 128 * 16; idx += 256) {
        int r = idx >> 4, c = (idx & 15) << 2;
        float4 f = *(const float4*)(qb + (size_t)r * DH + c);
        float4 o = make_float4(f2tf32(f.x), f2tf32(f.y), f2tf32(f.z), f2tf32(f.w));
        *(float4*)&sm[QS + r * STRIDE + c] = o;
    }

    float oacc[8][4];
    #pragma unroll
    for (int ch = 0; ch < 8; ch++)
        #pragma unroll
        for (int i = 0; i < 4; i++) oacc[ch][i] = 0.0f;
    float l0 = 0.0f, l1 = 0.0f;

    for (int t = 0; t < N_TILES; t++) {
        const int n0 = t * BN;
        __syncthreads();   // Q ready (t=0) / previous tile's smem reads done

        // ---- K,V tiles -> smem (tf32) ----
        for (int idx = tid; idx < 64 * 16; idx += 256) {
            int r = idx >> 4, c = (idx & 15) << 2;
            float4 f = *(const float4*)(kb + (size_t)r * S_LEN + n0 + c);
            *(float4*)&sm[KS + r * STRIDE + c] =
                make_float4(f2tf32(f.x), f2tf32(f.y), f2tf32(f.z), f2tf32(f.w));
            float4 h = *(const float4*)(vb + (size_t)(n0 + r) * DH + c);
            *(float4*)&sm[VS + r * STRIDE + c] =
                make_float4(f2tf32(h.x), f2tf32(h.y), f2tf32(h.z), f2tf32(h.w));
        }
        __syncthreads();

        // ---- S = Q @ K  (warp: 16 rows x 64 cols) ----
        float sacc[8][4];
        #pragma unroll
        for (int ch = 0; ch < 8; ch++)
            #pragma unroll
            for (int i = 0; i < 4; i++) sacc[ch][i] = 0.0f;

        #pragma unroll
        for (int ks = 0; ks < 8; ks++) {
            uint32_t a[4];
            const float* qr = &sm[QS + (wrow + g) * STRIDE + ks * 8 + tg];
            a[0] = __float_as_uint(qr[0]);
            a[1] = __float_as_uint(qr[8 * STRIDE]);
            a[2] = __float_as_uint(qr[4]);
            a[3] = __float_as_uint(qr[8 * STRIDE + 4]);
            #pragma unroll
            for (int ch = 0; ch < 8; ch++) {
                uint32_t b[2];
                b[0] = __float_as_uint(sm[KS + (ks * 8 + tg) * STRIDE + ch * 8 + g]);
                b[1] = __float_as_uint(sm[KS + (ks * 8 + tg + 4) * STRIDE + ch * 8 + g]);
                mma_tf32(sacc[ch], a, b);
            }
        }

        // ---- epilogue: scale + prev -> scores; p = exp(s); P -> smem ----
        {
            const float* pr0 = pb + (size_t)(wrow + g) * S_LEN + n0;
            const float* pr1 = pr0 + (size_t)8 * S_LEN;
            float* sr0 = sb + (size_t)(wrow + g) * S_LEN + n0;
            float* sr1 = sr0 + (size_t)8 * S_LEN;
            float* ps0 = &sm[PS + (wrow + g) * STRIDE];
            float* ps1 = ps0 + 8 * STRIDE;
            #pragma unroll
            for (int ch = 0; ch < 8; ch++) {
                int c = ch * 8 + 2 * tg;
                float2 pv0 = *(const float2*)(pr0 + c);
                float2 pv1 = *(const float2*)(pr1 + c);
                float s0 = fmaf(sacc[ch][0], QK_SCALE, pv0.x);
                float s1 = fmaf(sacc[ch][1], QK_SCALE, pv0.y);
                float s2 = fmaf(sacc[ch][2], QK_SCALE, pv1.x);
                float s3 = fmaf(sacc[ch][3], QK_SCALE, pv1.y);
                *(float2*)(sr0 + c) = make_float2(s0, s1);
                *(float2*)(sr1 + c) = make_float2(s2, s3);
                float p0 = fexp(s0), p1 = fexp(s1), p2 = fexp(s2), p3 = fexp(s3);
                l0 += p0 + p1;
                l1 += p2 + p3;
                *(float2*)(ps0 + c) = make_float2(f2tf32(p0), f2tf32(p1));
                *(float2*)(ps1 + c) = make_float2(f2tf32(p2), f2tf32(p3));
            }
        }
        __syncthreads();   // P ready for all warps

        // ---- O += P @ V ----
        #pragma unroll
        for (int ks = 0; ks < 8; ks++) {
            uint32_t a[4];
            const float* prw = &sm[PS + (wrow + g) * STRIDE + ks * 8 + tg];
            a[0] = __float_as_uint(prw[0]);
            a[1] = __float_as_uint(prw[8 * STRIDE]);
            a[2] = __float_as_uint(prw[4]);
            a[3] = __float_as_uint(prw[8 * STRIDE + 4]);
            #pragma unroll
            for (int ch = 0; ch < 8; ch++) {
                uint32_t b[2];
                b[0] = __float_as_uint(sm[VS + (ks * 8 + tg) * STRIDE + ch * 8 + g]);
                b[1] = __float_as_uint(sm[VS + (ks * 8 + tg + 4) * STRIDE + ch * 8 + g]);
                mma_tf32(oacc[ch], a, b);
            }
        }
    }

    // ---- finalize: reduce l across the 4 lanes sharing a row, out = O / l ----
    l0 += __shfl_xor_sync(0xffffffffu, l0, 1);
    l0 += __shfl_xor_sync(0xffffffffu, l0, 2);
    l1 += __shfl_xor_sync(0xffffffffu, l1, 1);
    l1 += __shfl_xor_sync(0xffffffffu, l1, 2);
    float inv0 = 1.0f / l0;
    float inv1 = 1.0f / l1;

    float* or0 = ob + (size_t)(wrow + g) * DH;
    float* or1 = or0 + (size_t)8 * DH;
    #pragma unroll
    for (int ch = 0; ch < 8; ch++) {
        int c = ch * 8 + 2 * tg;
        *(float2*)(or0 + c) = make_float2(oacc[ch][0] * inv0, oacc[ch][1] * inv0);
        *(float2*)(or1 + c) = make_float2(oacc[ch][2] * inv1, oacc[ch][3] * inv1);
    }
}

extern "C" void kernel_launch(void* const* d_in, const int* in_sizes, int n_in,
                              void* d_out, int out_size) {
    const float* q    = (const float*)d_in[0];
    const float* k    = (const float*)d_in[1];
    const float* v    = (const float*)d_in[2];
    const float* prev = (const float*)d_in[3];
    float* out_o = (float*)d_out;
    float* out_s = (float*)d_out + (size_t)32 * S_LEN * DH;

    cudaFuncSetAttribute(attn_mma_kernel, cudaFuncAttributeMaxDynamicSharedMemorySize, SMEM_BYTES);
    dim3 grid(S_LEN / BM, 32);
    attn_mma_kernel<<<grid, 256, SMEM_BYTES>>>(q, k, v, prev, out_o, out_s);
}